// round 17
// baseline (speedup 1.0000x reference)
#include <cuda_runtime.h>
#include <cstdint>

// ---------------------------------------------------------------------------
// out[i] = sum_{e: w_rows[e]==i} Param_W[w_params[e]] * x[w_cols[e]]
//          + Param_b[b_params[i]]
//
// N = 262144, E = 16.7M. Edge scatter (256-thr CTAs, 4 edges/thread, fp32,
// __ldg, REDs into __device__ g_acc) = 97% of the L1tex-wavefront ceiling.
// R15: the bias gather runs as 256 EXTRA CTAs inside the edge kernel's grid
// (plain stores into out — free, hidden in the 127us wave). The epilogue is
// then pure streaming: out4 += acc4; acc4 = 0 (no indirection chain).
// ---------------------------------------------------------------------------

#define NMAX   262144
#define EDGE_T 256

__device__ float g_acc[NMAX];   // zero at load; epilogue restores zero

// --- fused main kernel: edge quads + bias-store quads ----------------------
__global__ void __launch_bounds__(EDGE_T)
edge_bias_kernel(const float* __restrict__ x,
                 const float* __restrict__ Param_W,
                 const float* __restrict__ Param_b,
                 const int4*  __restrict__ rows4,
                 const int4*  __restrict__ cols4,
                 const int4*  __restrict__ params4,
                 const int4*  __restrict__ b_params4,
                 float4*      __restrict__ out4,
                 int E4, int N4)
{
    int t = blockIdx.x * EDGE_T + threadIdx.x;

    if (t < E4) {
        // ---- edge quad (proven optimal shape) ----
        int4 r = __ldcs(&rows4[t]);
        int4 c = __ldcs(&cols4[t]);
        int4 p = __ldcs(&params4[t]);

        float v0 = __ldg(&Param_W[p.x]) * __ldg(&x[c.x]);
        float v1 = __ldg(&Param_W[p.y]) * __ldg(&x[c.y]);
        float v2 = __ldg(&Param_W[p.z]) * __ldg(&x[c.z]);
        float v3 = __ldg(&Param_W[p.w]) * __ldg(&x[c.w]);

        atomicAdd(&g_acc[r.x], v0);
        atomicAdd(&g_acc[r.y], v1);
        atomicAdd(&g_acc[r.z], v2);
        atomicAdd(&g_acc[r.w], v3);
    } else if (t - E4 < N4) {
        // ---- bias quad: plain store into out (no one else writes out) ----
        int i = t - E4;
        int4 b = __ldcs(&b_params4[i]);
        float4 o;
        o.x = __ldg(&Param_b[b.x]);
        o.y = __ldg(&Param_b[b.y]);
        o.z = __ldg(&Param_b[b.z]);
        o.w = __ldg(&Param_b[b.w]);
        out4[i] = o;
    }
}

// --- epilogue: pure streaming  out += acc; acc = 0 -------------------------
__global__ void __launch_bounds__(256)
epilogue_stream_kernel(float4* __restrict__ out4, int N4)
{
    int i = blockIdx.x * blockDim.x + threadIdx.x;
    if (i < N4) {
        float4* acc4 = (float4*)&g_acc[i * 4];
        float4 a = *acc4;
        float4 o = out4[i];
        o.x += a.x;
        o.y += a.y;
        o.z += a.z;
        o.w += a.w;
        out4[i] = o;
        *acc4 = make_float4(0.f, 0.f, 0.f, 0.f);
    }
}

// --- fallback path (shape mismatch): plain two-pass ------------------------
__global__ void bias_only_kernel(const float* __restrict__ Param_b,
                                 const int*   __restrict__ b_params,
                                 float*       __restrict__ out, int N)
{
    int i = blockIdx.x * blockDim.x + threadIdx.x;
    if (i < N) out[i] = __ldg(&Param_b[b_params[i]]);
}

__global__ void edge_scatter_direct_kernel(const float* __restrict__ x,
                                           const float* __restrict__ Param_W,
                                           const int*   __restrict__ rows,
                                           const int*   __restrict__ cols,
                                           const int*   __restrict__ params,
                                           float*       __restrict__ out,
                                           int E)
{
    int e = blockIdx.x * blockDim.x + threadIdx.x;
    if (e < E) {
        float v = __ldg(&Param_W[params[e]]) * __ldg(&x[cols[e]]);
        atomicAdd(&out[rows[e]], v);
    }
}

extern "C" void kernel_launch(void* const* d_in, const int* in_sizes, int n_in,
                              void* d_out, int out_size)
{
    const float* x        = (const float*)d_in[0];
    const float* Param_W  = (const float*)d_in[1];
    const float* Param_b  = (const float*)d_in[2];
    const int*   w_rows   = (const int*)  d_in[3];
    const int*   w_cols   = (const int*)  d_in[4];
    const int*   w_params = (const int*)  d_in[5];
    const int*   b_params = (const int*)  d_in[6];
    float*       out      = (float*)d_out;

    const int N = out_size;       // 262144
    const int E = in_sizes[3];    // 16777216

    bool fused_ok = (N <= NMAX) && (E % 4 == 0) && (N % 4 == 0);

    if (!fused_ok) {
        bias_only_kernel<<<(N + 255) / 256, 256>>>(Param_b, b_params, out, N);
        edge_scatter_direct_kernel<<<(E + 255) / 256, 256>>>(
            x, Param_W, w_rows, w_cols, w_params, out, E);
        return;
    }

    int E4 = E / 4;   // 4194304
    int N4 = N / 4;   // 65536

    // 1) Fused kernel: 16384 edge CTAs + 256 bias CTAs, one wave structure.
    {
        int total  = E4 + N4;
        int blocks = (total + EDGE_T - 1) / EDGE_T;   // 16640
        edge_bias_kernel<<<blocks, EDGE_T>>>(
            x, Param_W, Param_b,
            (const int4*)w_rows, (const int4*)w_cols, (const int4*)w_params,
            (const int4*)b_params, (float4*)out, E4, N4);
    }

    // 2) Streaming epilogue: out += acc; acc = 0.
    {
        int threads = 256;
        int blocks  = (N4 + threads - 1) / threads;   // 256
        epilogue_stream_kernel<<<blocks, threads>>>((float4*)out, N4);
    }
}